// round 4
// baseline (speedup 1.0000x reference)
#include <cuda_runtime.h>

#define PI_F 3.14159265358979323846f

// Packed 4-bit species table (supports up to 65536 atoms)
__device__ unsigned g_pk[8192];

// ---------------------------------------------------------------------------
// Prep kernel: zero aev AND pack atomic_numbers into 4-bit nibbles.
// ---------------------------------------------------------------------------
__global__ void ani_prep_kernel(const int* __restrict__ an, int N, int PKW,
                                float4* __restrict__ aevv, long long aev_v4)
{
    long long t = (long long)blockIdx.x * blockDim.x + threadIdx.x;
    const float4 z = make_float4(0.f, 0.f, 0.f, 0.f);
    for (long long v = t; v < aev_v4; v += (long long)gridDim.x * blockDim.x)
        aevv[v] = z;
    if (t < PKW) {
        int base = (int)t << 3;
        unsigned v = 0;
#pragma unroll
        for (int k = 0; k < 8; k++) {
            int a = base + k;
            unsigned s = (a < N) ? (unsigned)an[a] : 0u;
            v |= (s & 15u) << (k * 4);
        }
        g_pk[t] = v;
    }
}

__device__ __forceinline__ float4 radial_half(float d, float base_k)
{
    float fc = (d <= 5.1f) ? (0.5f * __cosf((PI_F / 5.1f) * d) + 0.5f) : 0.0f;
    float a0 = d - base_k;
    float a1 = d - (base_k + 0.5375f);
    float a2 = d - (base_k + 1.075f);
    float a3 = d - (base_k + 1.6125f);
    return make_float4(0.25f * __expf(-19.7f * a0 * a0) * fc,
                       0.25f * __expf(-19.7f * a1 * a1) * fc,
                       0.25f * __expf(-19.7f * a2 * a2) * fc,
                       0.25f * __expf(-19.7f * a3 * a3) * fc);
}

// ---------------------------------------------------------------------------
// Fused kernel.
//   Radial role  : Rb persistent blocks (bid % S == 0), smem = packed species.
//   Angular role : everything else, smem = vec12 stage + output stage.
// ---------------------------------------------------------------------------
__global__ __launch_bounds__(128)
void ani_fused_kernel(const float* __restrict__ r_ij,
                      const int*   __restrict__ pidx,
                      const float* __restrict__ vec12,
                      float*       __restrict__ aev,
                      float*       __restrict__ ang,
                      int P, int T, int Rb, int S, int RT, int PKW, int fastload)
{
    __shared__ __align__(16) unsigned char smraw[25088];

    const int tid = threadIdx.x;
    const int b   = blockIdx.x;
    const int dv  = b / S;
    const bool is_rad = ((b % S) == 0) && (dv < Rb);

    if (is_rad) {
        // ======================= RADIAL (persistent) =======================
        unsigned* spk = reinterpret_cast<unsigned*>(smraw);
        for (int w = tid; w < PKW; w += 128) spk[w] = g_pk[w];
        __syncthreads();

        const int  l  = tid & 31;
        const int  q0 = l >> 1;
        const int  q1 = 16 + (l >> 1);
        const int  h  = l & 1;
        const float base_k = 0.8f + 2.15f * (float)h;   // ShfR[4h]

        for (int tile = dv; tile < RT; tile += Rb) {
            int p = tile * 128 + tid;
            float d = 0.0f; int rowA = 0, rowB = 0;
            bool valid = (p < P);
            if (valid) {
                d = __ldcs(r_ij + p);
                int i = pidx[p];
                int j = pidx[P + p];
                int si = (spk[i >> 3] >> ((i & 7) * 4)) & 7;
                int sj = (spk[j >> 3] >> ((j & 7) * 4)) & 7;
                rowA = i * 7 + sj;
                rowB = j * 7 + si;
            }
            unsigned vm = __ballot_sync(0xffffffffu, valid);
            if (vm == 0xffffffffu) {
                // transposed: lane pair (2m,2m+1) covers both halves of one row
                float d0  = __shfl_sync(0xffffffffu, d,    q0);
                float d1  = __shfl_sync(0xffffffffu, d,    q1);
                int   rA0 = __shfl_sync(0xffffffffu, rowA, q0);
                int   rA1 = __shfl_sync(0xffffffffu, rowA, q1);
                int   rB0 = __shfl_sync(0xffffffffu, rowB, q0);
                int   rB1 = __shfl_sync(0xffffffffu, rowB, q1);
                float4 g0 = radial_half(d0, base_k);
                float4 g1 = radial_half(d1, base_k);
                int off = 4 * h;
                atomicAdd(reinterpret_cast<float4*>(aev + (long long)rA0 * 8 + off), g0);
                atomicAdd(reinterpret_cast<float4*>(aev + (long long)rB0 * 8 + off), g0);
                atomicAdd(reinterpret_cast<float4*>(aev + (long long)rA1 * 8 + off), g1);
                atomicAdd(reinterpret_cast<float4*>(aev + (long long)rB1 * 8 + off), g1);
            } else if (valid) {
                float4 lo = radial_half(d, 0.8f);
                float4 hi = radial_half(d, 2.95f);
                float4* rA = reinterpret_cast<float4*>(aev + (long long)rowA * 8);
                float4* rB = reinterpret_cast<float4*>(aev + (long long)rowB * 8);
                atomicAdd(rA,     lo); atomicAdd(rA + 1, hi);
                atomicAdd(rB,     lo); atomicAdd(rB + 1, hi);
            }
        }
    } else {
        // =========================== ANGULAR ==============================
        int nr  = min(dv + 1, Rb);       // radial bids before this one
        int idx = b - nr;

        float* sf = reinterpret_cast<float*>(smraw);           // [128][36] stage
        float* sv = reinterpret_cast<float*>(smraw + 18432);   // 768-float vec stage

        const long long b0 = (long long)idx * 128;
        float x1, y1, z1, x2, y2, z2;
        bool in_range = (b0 + tid) < (long long)T;

        if (fastload && (b0 + 128 <= (long long)T)) {
            const float4* v1p = reinterpret_cast<const float4*>(vec12 + 3LL * b0);
            const float4* v2p = reinterpret_cast<const float4*>(vec12 + 3LL * T + 3LL * b0);
            float4* svv = reinterpret_cast<float4*>(sv);
#pragma unroll
            for (int u = tid; u < 192; u += 128)
                svv[u] = (u < 96) ? __ldcs(v1p + u) : __ldcs(v2p + (u - 96));
            __syncthreads();
            x1 = sv[3 * tid];       y1 = sv[3 * tid + 1];       z1 = sv[3 * tid + 2];
            x2 = sv[384 + 3 * tid]; y2 = sv[384 + 3 * tid + 1]; z2 = sv[384 + 3 * tid + 2];
        } else {
            long long t = b0 + tid;
            if (in_range) {
                const float* v1 = vec12 + 3LL * t;
                const float* v2 = vec12 + 3LL * T + 3LL * t;
                x1 = __ldcs(v1 + 0); y1 = __ldcs(v1 + 1); z1 = __ldcs(v1 + 2);
                x2 = __ldcs(v2 + 0); y2 = __ldcs(v2 + 1); z2 = __ldcs(v2 + 2);
            } else { x1 = y1 = z1 = x2 = y2 = z2 = 0.f; }
        }

        float out[32];
        if (in_range) {
            float d11 = fmaf(x1, x1, fmaf(y1, y1, z1 * z1));
            float d22 = fmaf(x2, x2, fmaf(y2, y2, z2 * z2));
            float d12 = fmaf(x1, x2, fmaf(y1, y2, z1 * z2));

            float rs1 = rsqrtf(d11);
            float rs2 = rsqrtf(d22);
            float d1  = d11 * rs1;
            float d2  = d22 * rs2;

            float cost = 0.95f * d12 * rs1 * rs2;                 // |cost| <= 0.95
            float sint = sqrtf(fmaxf(1.0f - cost * cost, 0.0f));  // theta in [0,pi]

            float fc1 = (d1 <= 3.5f) ? (0.5f * __cosf((PI_F / 3.5f) * d1) + 0.5f) : 0.0f;
            float fc2 = (d2 <= 3.5f) ? (0.5f * __cosf((PI_F / 3.5f) * d2) + 0.5f) : 0.0f;
            float fc2x = 2.0f * fc1 * fc2;

            float u = 0.5f * (d1 + d2);
            float frad[8];
#pragma unroll
            for (int a = 0; a < 8; a++) {
                float dd = u - (0.8f + 0.3375f * (float)a);   // ShfA[a]
                frad[a] = __expf(-12.5f * dd * dd);
            }

            const float CZ[4] = { 0.9238795325f,  0.3826834324f, -0.3826834324f, -0.9238795325f };
            const float SZ[4] = { 0.3826834324f,  0.9238795325f,  0.9238795325f,  0.3826834324f };

#pragma unroll
            for (int z = 0; z < 4; z++) {
                float xz = 0.5f * (1.0f + cost * CZ[z] + sint * SZ[z]);   // in [0,1]
                float fang = (xz > 0.0f) ? __powf(xz, 14.1f) : 0.0f;
                fang *= fc2x;
#pragma unroll
                for (int a = 0; a < 8; a++)
                    out[z * 8 + a] = fang * frad[a];
            }
        } else {
#pragma unroll
            for (int k = 0; k < 32; k++) out[k] = 0.0f;
        }

        // stage (STS.128, 144B rows: 16B-aligned & conflict-free) then flush
#pragma unroll
        for (int m = 0; m < 8; m++)
            *reinterpret_cast<float4*>(&sf[tid * 36 + m * 4]) =
                *reinterpret_cast<const float4*>(&out[m * 4]);

        __syncthreads();

        const long long base  = b0 * 32;
        const long long limit = (long long)T * 32;
        float4* outv = reinterpret_cast<float4*>(ang + base);
#pragma unroll
        for (int jj = tid; jj < 128 * 8; jj += 128) {
            if (base + (long long)jj * 4 < limit) {
                int q = jj >> 3;
                int k = (jj & 7) << 2;
                __stcs(&outv[jj], *reinterpret_cast<const float4*>(&sf[q * 36 + k]));
            }
        }
    }
}

// ---------------------------------------------------------------------------
// Inputs (metadata order): r_ij f32[P], pair_indices i32[2,P],
// atomic_numbers i32[N_ATOMS], vec12 f32[2,T,3].
// Output: aev f32[N_ATOMS*7, 8] followed by ang f32[T, 32].
// ---------------------------------------------------------------------------
extern "C" void kernel_launch(void* const* d_in, const int* in_sizes, int n_in,
                              void* d_out, int out_size)
{
    const float* r_ij  = (const float*)d_in[0];
    const int*   pidx  = (const int*)  d_in[1];
    const int*   an    = (const int*)  d_in[2];
    const float* vec12 = (const float*)d_in[3];

    const int P = in_sizes[0];
    const int T = in_sizes[3] / 6;
    const int N = in_sizes[2];
    const long long aev_elems = (long long)N * 7 * 8;

    float* aev = (float*)d_out;
    float* ang = aev + aev_elems;

    const int PKW = (N + 7) / 8;               // packed species words
    const int RT  = (P + 127) / 128;           // radial tiles
    const int A   = (T + 127) / 128;           // angular blocks
    int Rb = 296; if (Rb > RT) Rb = RT;        // persistent radial blocks
    int S  = (A + Rb) / Rb; if (S < 1) S = 1;  // radial spacing in launch order

    // fast cooperative vec12 load needs 16B alignment of the v2 section
    const int fastload = ((3LL * T) % 4 == 0) ? 1 : 0;
    const int can_pack = (PKW <= 6272) ? 1 : 0;  // fits 25KB smem + g_pk

    // zero aev + pack species in one prep kernel (aev_elems % 4 == 0 since *56)
    ani_prep_kernel<<<2048, 256>>>(an, N, can_pack ? PKW : 0,
                                   (float4*)aev, aev_elems / 4);
    // remainder floats (N*56 % 4 != 0 can't happen: 56 % 4 == 0)

    ani_fused_kernel<<<A + Rb, 128>>>(r_ij, pidx, vec12, aev, ang,
                                      P, T, Rb, S, RT, PKW, fastload);
}

// round 5
// speedup vs baseline: 1.2844x; 1.2844x over previous
#include <cuda_runtime.h>

#define PI_F 3.14159265358979323846f

__device__ __forceinline__ float4 radial_half(float d, float base_k)
{
    float fc = (d <= 5.1f) ? (0.5f * __cosf((PI_F / 5.1f) * d) + 0.5f) : 0.0f;
    float a0 = d - base_k;
    float a1 = d - (base_k + 0.5375f);
    float a2 = d - (base_k + 1.075f);
    float a3 = d - (base_k + 1.6125f);
    return make_float4(0.25f * __expf(-19.7f * a0 * a0) * fc,
                       0.25f * __expf(-19.7f * a1 * a1) * fc,
                       0.25f * __expf(-19.7f * a2 * a2) * fc,
                       0.25f * __expf(-19.7f * a3 * a3) * fc);
}

// ===========================================================================
// Fused kernel: every block does one angular tile (128 triplets) AND one
// radial tile (128 pairs). Radial uses a lane-pair layout so each RED.128
// covers 16 full 32B rows (paired lanes hit the two 16B halves of one row,
// same 128B line) -> half the atomic wavefronts of the naive layout.
// ===========================================================================
__global__ __launch_bounds__(128)
void ani_fused_kernel(const float* __restrict__ r_ij,
                      const int*   __restrict__ pidx,
                      const int*   __restrict__ an,
                      const float* __restrict__ vec12,
                      float*       __restrict__ aev,
                      float*       __restrict__ ang,
                      int P, int T)
{
    __shared__ float sf[128 * 36];   // 18432B: 144B rows, 16B-aligned, conflict-free

    const int tid = threadIdx.x;
    const int b   = blockIdx.x;

    // ----------------------- RADIAL (128 pairs) ---------------------------
    {
        const int   h      = tid & 1;                 // which 16B half
        const float base_k = 0.8f + 2.15f * (float)h; // ShfR[4h]
        const int   off    = 4 * h;
#pragma unroll
        for (int r = 0; r < 2; r++) {
            int q = b * 128 + r * 64 + (tid >> 1);    // pair index (lane-pair shared)
            if (q < P) {
                float d  = __ldcs(r_ij + q);
                int   i  = pidx[q];
                int   j  = pidx[P + q];
                int   si = an[i];
                int   sj = an[j];
                float4 g = radial_half(d, base_k);
                atomicAdd(reinterpret_cast<float4*>(aev + (long long)(i * 7 + sj) * 8 + off), g);
                atomicAdd(reinterpret_cast<float4*>(aev + (long long)(j * 7 + si) * 8 + off), g);
            }
        }
    }

    // ----------------------- ANGULAR (128 triplets) -----------------------
    const long long t = (long long)b * 128 + tid;
    float out[32];

    if (t < T) {
        const float* v1 = vec12 + 3LL * t;
        const float* v2 = vec12 + 3LL * T + 3LL * t;
        float x1 = __ldcs(v1 + 0), y1 = __ldcs(v1 + 1), z1 = __ldcs(v1 + 2);
        float x2 = __ldcs(v2 + 0), y2 = __ldcs(v2 + 1), z2 = __ldcs(v2 + 2);

        float d11 = fmaf(x1, x1, fmaf(y1, y1, z1 * z1));
        float d22 = fmaf(x2, x2, fmaf(y2, y2, z2 * z2));
        float d12 = fmaf(x1, x2, fmaf(y1, y2, z1 * z2));

        float rs1 = rsqrtf(d11);
        float rs2 = rsqrtf(d22);
        float d1  = d11 * rs1;
        float d2  = d22 * rs2;

        float cost = 0.95f * d12 * rs1 * rs2;                 // |cost| <= 0.95
        float sint = sqrtf(fmaxf(1.0f - cost * cost, 0.0f));  // theta in [0,pi]

        float fc1 = (d1 <= 3.5f) ? (0.5f * __cosf((PI_F / 3.5f) * d1) + 0.5f) : 0.0f;
        float fc2 = (d2 <= 3.5f) ? (0.5f * __cosf((PI_F / 3.5f) * d2) + 0.5f) : 0.0f;
        float fc2x = 2.0f * fc1 * fc2;

        float u = 0.5f * (d1 + d2);
        float frad[8];
#pragma unroll
        for (int a = 0; a < 8; a++) {
            float dd = u - (0.8f + 0.3375f * (float)a);   // ShfA[a]
            frad[a] = __expf(-12.5f * dd * dd);
        }

        // cos/sin of ShfZ = (z+0.5)*pi/4
        const float CZ[4] = { 0.9238795325f,  0.3826834324f, -0.3826834324f, -0.9238795325f };
        const float SZ[4] = { 0.3826834324f,  0.9238795325f,  0.9238795325f,  0.3826834324f };

#pragma unroll
        for (int z = 0; z < 4; z++) {
            float xz = 0.5f * (1.0f + cost * CZ[z] + sint * SZ[z]);   // in [0,1]
            float fang = (xz > 0.0f) ? __powf(xz, 14.1f) : 0.0f;
            fang *= fc2x;
#pragma unroll
            for (int a = 0; a < 8; a++)
                out[z * 8 + a] = fang * frad[a];
        }
    } else {
#pragma unroll
        for (int k = 0; k < 32; k++) out[k] = 0.0f;
    }

    // Stage via STS.128 then flush fully coalesced, evict-first (stream is
    // never re-read; keep L2 for the aev atomic table).
#pragma unroll
    for (int m = 0; m < 8; m++)
        *reinterpret_cast<float4*>(&sf[tid * 36 + m * 4]) =
            *reinterpret_cast<const float4*>(&out[m * 4]);

    __syncthreads();

    const long long base  = (long long)b * (128 * 32);
    const long long limit = (long long)T * 32;
    if (base < limit) {
        float4* outv = reinterpret_cast<float4*>(ang + base);
#pragma unroll
        for (int jj = tid; jj < 128 * 8; jj += 128) {
            if (base + (long long)jj * 4 < limit) {
                int q = jj >> 3;
                int k = (jj & 7) << 2;
                __stcs(&outv[jj], *reinterpret_cast<const float4*>(&sf[q * 36 + k]));
            }
        }
    }
}

// ---------------------------------------------------------------------------
// Inputs (metadata order): r_ij f32[P], pair_indices i32[2,P],
// atomic_numbers i32[N_ATOMS], vec12 f32[2,T,3].
// Output: aev f32[N_ATOMS*7, 8] followed by ang f32[T, 32].
// ---------------------------------------------------------------------------
extern "C" void kernel_launch(void* const* d_in, const int* in_sizes, int n_in,
                              void* d_out, int out_size)
{
    const float* r_ij  = (const float*)d_in[0];
    const int*   pidx  = (const int*)  d_in[1];
    const int*   an    = (const int*)  d_in[2];
    const float* vec12 = (const float*)d_in[3];

    const int P = in_sizes[0];
    const int T = in_sizes[3] / 6;
    const long long aev_elems = (long long)in_sizes[2] * 7 * 8;

    float* aev = (float*)d_out;
    float* ang = aev + aev_elems;

    const int A  = (T + 127) / 128;   // angular tiles
    const int R  = (P + 127) / 128;   // radial tiles (128 pairs each)
    const int G  = (A > R) ? A : R;

    // aev must start at zero each replay (d_out is poisoned before timing)
    cudaMemsetAsync(d_out, 0, aev_elems * sizeof(float), 0);

    ani_fused_kernel<<<G, 128>>>(r_ij, pidx, an, vec12, aev, ang, P, T);
}